// round 9
// baseline (speedup 1.0000x reference)
#include <cuda_runtime.h>
#include <math.h>

#define BB 16
#define SS 1024
#define NIN 7
#define NHID 28
#define HEADS 7
#define HD 4

// Scratch (device globals — no allocation allowed)
__device__ float g_Q [BB*HEADS*SS*HD];
__device__ float g_K [BB*HEADS*SS*HD];
__device__ float g_V [BB*HEADS*SS*HD];
__device__ float g_AO[BB*SS*NHID];
__device__ float g_Q2[BB*SS*NHID];
__device__ float g_K2[BB*SS*NHID];

// ---------------------------------------------------------------------------
// helpers
// ---------------------------------------------------------------------------
typedef unsigned long long u64;
__device__ __forceinline__ float ex2(float x) {            // single MUFU.EX2
    float r; asm("ex2.approx.ftz.f32 %0, %1;" : "=f"(r) : "f"(x)); return r;
}
__device__ __forceinline__ u64 pk2(float a, float b) {
    u64 r; asm("mov.b64 %0, {%1,%2};" : "=l"(r) : "f"(a), "f"(b)); return r;
}
__device__ __forceinline__ void up2(u64 v, float& a, float& b) {
    asm("mov.b64 {%0,%1}, %2;" : "=f"(a), "=f"(b) : "l"(v));
}
__device__ __forceinline__ u64 f2fma(u64 a, u64 b, u64 c) {
    u64 d; asm("fma.rn.f32x2 %0, %1, %2, %3;" : "=l"(d) : "l"(a), "l"(b), "l"(c)); return d;
}
__device__ __forceinline__ u64 f2mul(u64 a, u64 b) {
    u64 d; asm("mul.rn.f32x2 %0, %1, %2;" : "=l"(d) : "l"(a), "l"(b)); return d;
}
__device__ __forceinline__ u64 f2add(u64 a, u64 b) {
    u64 d; asm("add.rn.f32x2 %0, %1, %2;" : "=l"(d) : "l"(a), "l"(b)); return d;
}

// ---------------------------------------------------------------------------
// K1: QKV projection. 1 thread per (b,s) row. Q/K/V stored [B,H,S,4] (float4).
// ---------------------------------------------------------------------------
__global__ void k_qkv(const float* __restrict__ x,
                      const float* __restrict__ Wq, const float* __restrict__ bq,
                      const float* __restrict__ Wk, const float* __restrict__ bk,
                      const float* __restrict__ Wv, const float* __restrict__ bv) {
    __shared__ float sw[672];
    int tid = threadIdx.x;
    for (int i = tid; i < 196; i += blockDim.x) {
        sw[i] = Wq[i]; sw[224 + i] = Wk[i]; sw[448 + i] = Wv[i];
    }
    if (tid < 28) { sw[196 + tid] = bq[tid]; sw[420 + tid] = bk[tid]; sw[644 + tid] = bv[tid]; }
    __syncthreads();

    int r = blockIdx.x * blockDim.x + tid;        // 0..16383
    int b = r >> 10, s = r & 1023;

    float xv[7];
#pragma unroll
    for (int i = 0; i < 7; i++) xv[i] = x[r * 7 + i];

#pragma unroll
    for (int h = 0; h < 7; h++) {
        float qa[4], ka[4], va[4];
#pragma unroll
        for (int d = 0; d < 4; d++) {
            int j = h * 4 + d;
            float aq = sw[196 + j], ak = sw[420 + j], av = sw[644 + j];
#pragma unroll
            for (int i = 0; i < 7; i++) {
                float xi = xv[i];
                aq += xi * sw[i * 28 + j];
                ak += xi * sw[224 + i * 28 + j];
                av += xi * sw[448 + i * 28 + j];
            }
            qa[d] = aq; ka[d] = ak; va[d] = av;
        }
        int o = (b * 7 + h) * 1024 + s;
        reinterpret_cast<float4*>(g_Q)[o] = make_float4(qa[0], qa[1], qa[2], qa[3]);
        reinterpret_cast<float4*>(g_K)[o] = make_float4(ka[0], ka[1], ka[2], ka[3]);
        reinterpret_cast<float4*>(g_V)[o] = make_float4(va[0], va[1], va[2], va[3]);
    }
}

// ---------------------------------------------------------------------------
// K2: first attention — f32x2 packed over k-PAIRS (not q-pairs).
// Kt/Vt in smem transposed-paired: Kt[2p].x=(K[2p][0],K[2p+1][0]), etc.
// q duplicated in registers, so each iter does scores+exp+PV for 2 k's
// with 9 FMA-pipe ops. 1 q row/thread -> 128-q chunks -> grid 896;
// smem 32KB (no duplication) -> 7 CTA/SM, 28 warps/SM.
// ---------------------------------------------------------------------------
__global__ void __launch_bounds__(128) k_attn1() {
    __shared__ ulonglong2 Kt[1024];
    __shared__ ulonglong2 Vt[1024];
    int b = blockIdx.z, h = blockIdx.y, chunk = blockIdx.x;   // chunk in [0,8)
    int bh = b * 7 + h;
    const float4* Kg = reinterpret_cast<const float4*>(g_K) + bh * 1024;
    const float4* Vg = reinterpret_cast<const float4*>(g_V) + bh * 1024;
    for (int p = threadIdx.x; p < 512; p += 128) {
        float4 a = Kg[2*p], c2 = Kg[2*p+1];
        Kt[2*p]   = make_ulonglong2(pk2(a.x, c2.x), pk2(a.y, c2.y));
        Kt[2*p+1] = make_ulonglong2(pk2(a.z, c2.z), pk2(a.w, c2.w));
        float4 va = Vg[2*p], vc = Vg[2*p+1];
        Vt[2*p]   = make_ulonglong2(pk2(va.x, vc.x), pk2(va.y, vc.y));
        Vt[2*p+1] = make_ulonglong2(pk2(va.z, vc.z), pk2(va.w, vc.w));
    }
    __syncthreads();

    int q = chunk * 128 + threadIdx.x;
    float4 qv = reinterpret_cast<const float4*>(g_Q)[bh * 1024 + q];
    const float c = 0.5f * 1.4426950408889634f;  // 1/sqrt(4) * log2(e)
    u64 qd0 = pk2(qv.x * c, qv.x * c);
    u64 qd1 = pk2(qv.y * c, qv.y * c);
    u64 qd2 = pk2(qv.z * c, qv.z * c);
    u64 qd3 = pk2(qv.w * c, qv.w * c);

    u64 acc0 = 0ull, acc1 = 0ull, acc2 = 0ull, acc3 = 0ull, l2 = 0ull;
#pragma unroll 4
    for (int p = 0; p < 512; p++) {
        ulonglong2 k01 = Kt[2*p];
        ulonglong2 k23 = Kt[2*p+1];
        u64 s2 = f2mul(qd0, k01.x);            // (s_k, s_k+1) partial
        s2 = f2fma(qd1, k01.y, s2);
        s2 = f2fma(qd2, k23.x, s2);
        s2 = f2fma(qd3, k23.y, s2);
        float sa, sb; up2(s2, sa, sb);
        u64 p2 = pk2(ex2(sa), ex2(sb));        // (p_k, p_k+1)
        ulonglong2 v01 = Vt[2*p];
        ulonglong2 v23 = Vt[2*p+1];
        acc0 = f2fma(p2, v01.x, acc0);         // (even-k part, odd-k part)
        acc1 = f2fma(p2, v01.y, acc1);
        acc2 = f2fma(p2, v23.x, acc2);
        acc3 = f2fma(p2, v23.y, acc3);
        l2 = f2add(l2, p2);
    }
    float le, lo; up2(l2, le, lo);
    float inv = 1.f / (le + lo);
    float e0,o0,e1,o1,e2,o2,e3,o3;
    up2(acc0, e0, o0); up2(acc1, e1, o1); up2(acc2, e2, o2); up2(acc3, e3, o3);
    *reinterpret_cast<float4*>(g_AO + ((b * 1024 + q) * 28 + h * 4)) =
        make_float4((e0+o0)*inv, (e1+o1)*inv, (e2+o2)*inv, (e3+o3)*inv);
}

// ---------------------------------------------------------------------------
// K3: LayerNorm(28) + FFN(28->7) + ReLU + residual -> out7 (d_out head),
// then Q2/K2 projections (7->28) into scratch. 1 thread per row.
// ---------------------------------------------------------------------------
__global__ void k_lnffn(const float* __restrict__ x,
                        const float* __restrict__ lnw, const float* __restrict__ lnb,
                        const float* __restrict__ W1,  const float* __restrict__ b1,
                        const float* __restrict__ Wq2, const float* __restrict__ bq2,
                        const float* __restrict__ Wk2, const float* __restrict__ bk2,
                        float* __restrict__ out7) {
    __shared__ float s_lnw[28], s_lnb[28], s_W1[196], s_b1[7];
    __shared__ float s_Wq2[196], s_bq2[28], s_Wk2[196], s_bk2[28];
    int tid = threadIdx.x;
    for (int i = tid; i < 196; i += blockDim.x) { s_W1[i] = W1[i]; s_Wq2[i] = Wq2[i]; s_Wk2[i] = Wk2[i]; }
    if (tid < 28) { s_lnw[tid] = lnw[tid]; s_lnb[tid] = lnb[tid]; s_bq2[tid] = bq2[tid]; s_bk2[tid] = bk2[tid]; }
    if (tid < 7)  { s_b1[tid] = b1[tid]; }
    __syncthreads();

    int r = blockIdx.x * blockDim.x + tid;
    float a[28];
    const float4* ap = reinterpret_cast<const float4*>(g_AO + r * 28);
#pragma unroll
    for (int i = 0; i < 7; i++) {
        float4 t = ap[i];
        a[4*i] = t.x; a[4*i+1] = t.y; a[4*i+2] = t.z; a[4*i+3] = t.w;
    }
    float mu = 0.f;
#pragma unroll
    for (int j = 0; j < 28; j++) mu += a[j];
    mu *= (1.f / 28.f);
    float var = 0.f;
#pragma unroll
    for (int j = 0; j < 28; j++) { float d = a[j] - mu; var += d * d; }
    var *= (1.f / 28.f);
    float rs = rsqrtf(var + 1e-5f);

    float y[28];
#pragma unroll
    for (int j = 0; j < 28; j++) y[j] = (a[j] - mu) * rs * s_lnw[j] + s_lnb[j];

    float z[7];
#pragma unroll
    for (int i = 0; i < 7; i++) {
        float t = s_b1[i];
#pragma unroll
        for (int j = 0; j < 28; j++) t += y[j] * s_W1[j * 7 + i];
        t = fmaxf(t, 0.f) + x[r * 7 + i];
        z[i] = t;
        out7[r * 7 + i] = t;
    }
#pragma unroll
    for (int j = 0; j < 28; j++) {
        float tq = s_bq2[j], tk = s_bk2[j];
#pragma unroll
        for (int i = 0; i < 7; i++) {
            tq += z[i] * s_Wq2[i * 28 + j];
            tk += z[i] * s_Wk2[i * 28 + j];
        }
        g_Q2[r * 28 + j] = tq;
        g_K2[r * 28 + j] = tk;
    }
}

// ---------------------------------------------------------------------------
// K4: second attention weights — K2 in registers, Q2 broadcast from smem.
// Block = 512 thr (16 warps). Thread owns ADJACENT k rows {2m, 2m+1}
// (m = warp*32+lane) so (pA,pB) packs into one STG.64 (contiguous 256B/warp).
// No per-q shfl: row sums are computed in the normalize pass, where each warp
// owns 2 whole q-rows (8 LDG.128/lane, sum, 5 shfl, scale, 8 STG.128).
// ---------------------------------------------------------------------------
__global__ void __launch_bounds__(512, 1) k_attn2(float* __restrict__ out) {
    __shared__ float sQ[32 * 28];          // q tile (scaled)

    int b = blockIdx.y, tile = blockIdx.x;             // 32 tiles of 32 q rows
    int warp = threadIdx.x >> 5, lane = threadIdx.x & 31;
    const float SC2 = 1.4426950408889634f / 2.6457513110645906f; // log2(e)/sqrt(7)

    // Load + scale Q2 tile into smem
    for (int t = threadIdx.x; t < 32 * 28; t += 512)
        sQ[t] = g_Q2[(b * 1024 + tile * 32) * 28 + t] * SC2;

    // This thread's two adjacent K2 rows -> registers (once per block)
    int m = warp * 32 + lane;                           // 0..511
    ulonglong2 kA[7], kB[7];
    {
        const ulonglong2* a = reinterpret_cast<const ulonglong2*>(g_K2 + (b * 1024 + 2 * m) * 28);
        const ulonglong2* c = reinterpret_cast<const ulonglong2*>(g_K2 + (b * 1024 + 2 * m + 1) * 28);
#pragma unroll
        for (int j = 0; j < 7; j++) { kA[j] = a[j]; kB[j] = c[j]; }
    }
    __syncthreads();

    float* obase = out + (b * 1024 + tile * 32) * 1024;

#pragma unroll 2
    for (int q = 0; q < 32; q++) {
        const ulonglong2* qp = reinterpret_cast<const ulonglong2*>(sQ + q * 28);
        ulonglong2 qv[7];
#pragma unroll
        for (int j = 0; j < 7; j++) qv[j] = qp[j];      // broadcast LDS (N=1)

        u64 accA = f2mul(qv[0].x, kA[0].x);
        u64 accB = f2mul(qv[0].x, kB[0].x);
        accA = f2fma(qv[0].y, kA[0].y, accA);  accB = f2fma(qv[0].y, kB[0].y, accB);
        accA = f2fma(qv[1].x, kA[1].x, accA);  accB = f2fma(qv[1].x, kB[1].x, accB);
        accA = f2fma(qv[1].y, kA[1].y, accA);  accB = f2fma(qv[1].y, kB[1].y, accB);
        accA = f2fma(qv[2].x, kA[2].x, accA);  accB = f2fma(qv[2].x, kB[2].x, accB);
        accA = f2fma(qv[2].y, kA[2].y, accA);  accB = f2fma(qv[2].y, kB[2].y, accB);
        accA = f2fma(qv[3].x, kA[3].x, accA);  accB = f2fma(qv[3].x, kB[3].x, accB);
        accA = f2fma(qv[3].y, kA[3].y, accA);  accB = f2fma(qv[3].y, kB[3].y, accB);
        accA = f2fma(qv[4].x, kA[4].x, accA);  accB = f2fma(qv[4].x, kB[4].x, accB);
        accA = f2fma(qv[4].y, kA[4].y, accA);  accB = f2fma(qv[4].y, kB[4].y, accB);
        accA = f2fma(qv[5].x, kA[5].x, accA);  accB = f2fma(qv[5].x, kB[5].x, accB);
        accA = f2fma(qv[5].y, kA[5].y, accA);  accB = f2fma(qv[5].y, kB[5].y, accB);
        accA = f2fma(qv[6].x, kA[6].x, accA);  accB = f2fma(qv[6].x, kB[6].x, accB);
        accA = f2fma(qv[6].y, kA[6].y, accA);  accB = f2fma(qv[6].y, kB[6].y, accB);

        float aLo, aHi, bLo, bHi;
        up2(accA, aLo, aHi); up2(accB, bLo, bHi);
        float pA = ex2(aLo + aHi);
        float pB = ex2(bLo + bHi);

        // one STG.64: (pA, pB) at columns (2m, 2m+1)
        *reinterpret_cast<u64*>(&obase[q * 1024 + 2 * m]) = pk2(pA, pB);
    }
    __syncthreads();   // make all warps' global p-writes visible block-wide

    // Normalize pass: each warp owns q-rows {warp, warp+16}.
#pragma unroll
    for (int rr = 0; rr < 2; rr++) {
        int q = warp + rr * 16;
        float4* row = reinterpret_cast<float4*>(obase + q * 1024);
        float4 v[8];
#pragma unroll
        for (int i = 0; i < 8; i++) v[i] = row[i * 32 + lane];
        float s = 0.f;
#pragma unroll
        for (int i = 0; i < 8; i++) s += (v[i].x + v[i].y) + (v[i].z + v[i].w);
#pragma unroll
        for (int o = 16; o > 0; o >>= 1)
            s += __shfl_xor_sync(0xffffffffu, s, o);
        float iv = 1.f / s;
#pragma unroll
        for (int i = 0; i < 8; i++) {
            v[i].x *= iv; v[i].y *= iv; v[i].z *= iv; v[i].w *= iv;
            row[i * 32 + lane] = v[i];
        }
    }
}

// ---------------------------------------------------------------------------
extern "C" void kernel_launch(void* const* d_in, const int* in_sizes, int n_in,
                              void* d_out, int out_size) {
    const float* x    = (const float*)d_in[0];
    const float* Wq   = (const float*)d_in[1];
    const float* bq   = (const float*)d_in[2];
    const float* Wk   = (const float*)d_in[3];
    const float* bk   = (const float*)d_in[4];
    const float* Wv   = (const float*)d_in[5];
    const float* bv   = (const float*)d_in[6];
    const float* lnw  = (const float*)d_in[7];
    const float* lnb  = (const float*)d_in[8];
    const float* W1   = (const float*)d_in[9];
    const float* b1   = (const float*)d_in[10];
    const float* Wq2  = (const float*)d_in[11];
    const float* bq2  = (const float*)d_in[12];
    const float* Wk2  = (const float*)d_in[13];
    const float* bk2  = (const float*)d_in[14];
    float* out = (float*)d_out;

    k_qkv<<<128, 128>>>(x, Wq, bq, Wk, bk, Wv, bv);
    k_attn1<<<dim3(8, 7, 16), 128>>>();
    k_lnffn<<<128, 128>>>(x, lnw, lnb, W1, b1, Wq2, bq2, Wk2, bk2, out);
    k_attn2<<<dim3(32, 16), 512>>>(out + BB * SS * NIN);
}